// round 4
// baseline (speedup 1.0000x reference)
#include <cuda_runtime.h>
#include <cstdint>
#include <cstddef>

#define BATCH 16
#define CIN   128
#define HI    128
#define WIN   128
#define HO    64
#define WO    64
#define PADW  66

// ---------------- scratch (device globals; no allocation) ----------------
__device__ float g_pooled[BATCH * CIN * HO * WO];       // 33.5 MB (skip path)
__device__ uint4 g_abin4[2 * BATCH * PADW * PADW * 8];  // 17.8 MB padded int8 +-1/0, ch-innermost
__device__ uint4 g_wbin4[2 * 9 * 128 * 8];              // [br][tap][oc][ch] int8 sign
__device__ float g_scale[2 * 128];

// ---------------- helpers ----------------
__device__ __forceinline__ uint32_t smem_to_u32(const void* p) {
    uint32_t a;
    asm("{ .reg .u64 t; cvta.to.shared.u64 t, %1; cvt.u32.u64 %0, t; }" : "=r"(a) : "l"(p));
    return a;
}

#define CP_ASYNC16(dst, src) \
    asm volatile("cp.async.cg.shared.global [%0], [%1], 16;" :: "r"((uint32_t)(dst)), "l"(src) : "memory")
#define CP_COMMIT() asm volatile("cp.async.commit_group;" ::: "memory")
#define CP_WAIT(N)  asm volatile("cp.async.wait_group %0;" :: "n"(N) : "memory")

__device__ __forceinline__ void ldsm4(unsigned* r, uint32_t addr) {
    asm volatile("ldmatrix.sync.aligned.m8n8.x4.shared.b16 {%0,%1,%2,%3}, [%4];"
                 : "=r"(r[0]), "=r"(r[1]), "=r"(r[2]), "=r"(r[3]) : "r"(addr));
}

__device__ __forceinline__ void imma(int* c, const unsigned* a, const unsigned* b) {
    asm volatile("mma.sync.aligned.m16n8k32.row.col.s32.s8.s8.s32 "
                 "{%0,%1,%2,%3}, {%4,%5,%6,%7}, {%8,%9}, {%0,%1,%2,%3};"
                 : "+r"(c[0]), "+r"(c[1]), "+r"(c[2]), "+r"(c[3])
                 : "r"(a[0]), "r"(a[1]), "r"(a[2]), "r"(a[3]), "r"(b[0]), "r"(b[1]));
}

// ---------------- kernel 1: weight prep (int8 signs + scale) ----------------
__global__ void wprep_kernel(const float* __restrict__ W1, const float* __restrict__ W2) {
    int bid = blockIdx.x;
    int br = bid >> 7, o = bid & 127;
    const float* W = br ? W2 : W1;
    int i = threadIdx.x;

    float w[9];
    float asum = 0.f;
#pragma unroll
    for (int t = 0; t < 9; ++t) {
        w[t] = W[(o * 128 + i) * 9 + t];
        asum += fabsf(w[t]);
    }

    __shared__ float red[128];
    red[i] = asum;
    __syncthreads();
    for (int s = 64; s > 0; s >>= 1) {
        if (i < s) red[i] += red[i + s];
        __syncthreads();
    }

    char* wb = reinterpret_cast<char*>(g_wbin4);
#pragma unroll
    for (int t = 0; t < 9; ++t) {
        char s = (w[t] > 0.f) ? 1 : ((w[t] < 0.f) ? -1 : 0);
        wb[((br * 9 + t) * 128 + o) * 128 + i] = s;
    }
    if (i == 0) g_scale[br * 128 + o] = red[0] * (1.0f / 1152.0f);
}

// ---------------- kernel 2: fused 2x2 avg pool + binarize to padded int8 ----------------
// block (32,8); 32 x-pixels at one (b, y)
__global__ void poolbin_kernel(const float* __restrict__ x,
                               const float* __restrict__ mvk1, const float* __restrict__ mvb1,
                               const float* __restrict__ mvk2, const float* __restrict__ mvb2) {
    __shared__ char sm[2][32][128];
    int tx = threadIdx.x, ty = threadIdx.y;
    int tid = ty * 32 + tx;
    int b = blockIdx.z, y = blockIdx.y, x0 = blockIdx.x * 32;
    int xo = x0 + tx;
    const float2* p = reinterpret_cast<const float2*>(x);

#pragma unroll
    for (int i = 0; i < 16; ++i) {
        int c = ty + i * 8;
        int base = ((b * CIN + c) * HI + 2 * y) * (WIN / 2) + xo;
        float2 r0 = p[base];
        float2 r1 = p[base + WIN / 2];
        float v = 0.25f * ((r0.x + r0.y) + (r1.x + r1.y));
        g_pooled[((b * CIN + c) * HO + y) * WO + xo] = v;
        float a1 = v * mvk1[c] + mvb1[c];
        float a2 = v * mvk2[c] + mvb2[c];
        sm[0][tx][c] = (a1 > 0.f) ? 1 : ((a1 < 0.f) ? -1 : 0);
        sm[1][tx][c] = (a2 > 0.f) ? 1 : ((a2 < 0.f) ? -1 : 0);
    }
    __syncthreads();

    const uint4* s4 = reinterpret_cast<const uint4*>(sm);
#pragma unroll
    for (int k = tid; k < 512; k += 256) {
        int br = k >> 8, px = (k >> 3) & 31, w = k & 7;
        int f = ((br * BATCH + b) * PADW + (y + 1)) * PADW + (x0 + px + 1);
        g_abin4[f * 8 + w] = s4[k];
    }
}

// ---------------- kernel 3: zero padded borders ----------------
__global__ void zb_kernel() {
    int t = blockIdx.x * blockDim.x + threadIdx.x;
    if (t >= 32 * 260 * 8) return;
    int w = t & 7;
    int pidx = t >> 3;
    int e = pidx % 260, bb = pidx / 260;
    int py, px;
    if (e < 66)       { py = 0;  px = e; }
    else if (e < 132) { py = 65; px = e - 66; }
    else if (e < 196) { py = e - 132 + 1; px = 0; }
    else              { py = e - 196 + 1; px = 65; }
    int f = (bb * PADW + py) * PADW + px;
    g_abin4[f * 8 + w] = make_uint4(0, 0, 0, 0);
}

// ---------------- kernel 4: int8 IMMA conv + RPReLU + skip + concat ----------------
// grid (ygroup=32, b=16, br=2); 256 threads; block tile 128px x 128oc, K=9x128
#define ASTRIDE 144
#define ATILE   (128 * ASTRIDE)   // 18432
#define BUFSZ   (2 * ATILE)       // A + B per stage
#define SM_DYN  (2 * BUFSZ)       // 73728 double-buffered

__global__ __launch_bounds__(256) void conv_imma_kernel(
    const float* __restrict__ pb0_1, const float* __restrict__ alpha1, const float* __restrict__ pb1_1,
    const float* __restrict__ pb0_2, const float* __restrict__ alpha2, const float* __restrict__ pb1_2,
    float* __restrict__ out) {

    extern __shared__ char smem[];
    __shared__ float ps[512];
    uint32_t sb = smem_to_u32(smem);
    int tid = threadIdx.x, wid = tid >> 5, lane = tid & 31;
    int ygroup = blockIdx.x, b = blockIdx.y, br = blockIdx.z;
    int y0 = ygroup * 2;

    if (tid < 128) {
        ps[tid]       = g_scale[br * 128 + tid];
        ps[128 + tid] = br ? pb0_2[tid]  : pb0_1[tid];
        ps[256 + tid] = br ? alpha2[tid] : alpha1[tid];
        ps[384 + tid] = br ? pb1_2[tid]  : pb1_1[tid];
    }

    const char* ag = reinterpret_cast<const char*>(g_abin4) +
                     (size_t)(br * BATCH + b) * (PADW * PADW * 128);
    const char* wg = reinterpret_cast<const char*>(g_wbin4) + (size_t)br * 9 * 128 * 128;

    // stage one tap (A: 128px x 128ch, B: 128oc x 128ch) into buffer `buf`
    auto loadtap = [&](int tap, int buf) {
        int dy = tap / 3 - 1, dx = tap % 3 - 1;
        uint32_t abase = sb + buf * BUFSZ;
        uint32_t bbase = abase + ATILE;
#pragma unroll
        for (int i = 0; i < 4; ++i) {
            int c = tid + 256 * i;
            int row = c >> 3, byte = (c & 7) * 16;
            int py = y0 + (row >> 6) + dy + 1;
            int px = (row & 63) + dx + 1;
            CP_ASYNC16(abase + row * ASTRIDE + byte, ag + (py * PADW + px) * 128 + byte);
            CP_ASYNC16(bbase + row * ASTRIDE + byte, wg + (tap * 128 + row) * 128 + byte);
        }
    };

    loadtap(0, 0);
    CP_COMMIT();

    int acc[4][4][4];
#pragma unroll
    for (int a = 0; a < 4; ++a)
#pragma unroll
        for (int bq = 0; bq < 4; ++bq)
#pragma unroll
            for (int cq = 0; cq < 4; ++cq) acc[a][bq][cq] = 0;

    int mrow = (wid & 1) * 64, ncol = (wid >> 1) * 32;
    // ldmatrix per-thread source rows (x4 tiles: lanes 0-7/8-15/16-23/24-31)
    uint32_t a_r = (lane & 7) + ((lane >> 3) & 1) * 8;   // row within 16-row m-tile
    uint32_t a_byte = (lane >> 4) * 16;                  // k-halves 0/16
    uint32_t b_r = (lane & 7) + (lane >> 4) * 8;         // n within 16-col pair
    uint32_t b_byte = ((lane >> 3) & 1) * 16;

    for (int tap = 0; tap < 9; ++tap) {
        int buf = tap & 1;
        if (tap < 8) { loadtap(tap + 1, buf ^ 1); CP_COMMIT(); CP_WAIT(1); }
        else         { CP_WAIT(0); }
        __syncthreads();

        uint32_t A0 = sb + buf * BUFSZ + (mrow + a_r) * ASTRIDE + a_byte;
        uint32_t B0 = sb + buf * BUFSZ + ATILE + (ncol + b_r) * ASTRIDE + b_byte;
#pragma unroll
        for (int ks = 0; ks < 4; ++ks) {
            unsigned af[4][4], bf[2][4];
#pragma unroll
            for (int mi = 0; mi < 4; ++mi) ldsm4(af[mi], A0 + mi * (16 * ASTRIDE) + ks * 32);
#pragma unroll
            for (int n2 = 0; n2 < 2; ++n2) ldsm4(bf[n2], B0 + n2 * (16 * ASTRIDE) + ks * 32);
#pragma unroll
            for (int mi = 0; mi < 4; ++mi) {
                imma(acc[mi][0], af[mi], &bf[0][0]);
                imma(acc[mi][1], af[mi], &bf[0][2]);
                imma(acc[mi][2], af[mi], &bf[1][0]);
                imma(acc[mi][3], af[mi], &bf[1][2]);
            }
        }
        __syncthreads();
    }

    // ---- epilogue ----
    int g = lane >> 2, tig = lane & 3;
    float* outp = out + ((size_t)b * 256 + br * 128) * 4096 + y0 * 64;
    const float* skp = g_pooled + ((size_t)b * 128) * 4096 + y0 * 64;

#pragma unroll
    for (int ni = 0; ni < 4; ++ni) {
        int oc0 = ncol + ni * 8 + 2 * tig;
        float sc0 = ps[oc0],       sc1 = ps[oc0 + 1];
        float p00 = ps[128 + oc0], p01 = ps[128 + oc0 + 1];
        float al0 = ps[256 + oc0], al1 = ps[256 + oc0 + 1];
        float p10 = ps[384 + oc0], p11 = ps[384 + oc0 + 1];
#pragma unroll
        for (int mi = 0; mi < 4; ++mi) {
#pragma unroll
            for (int h = 0; h < 2; ++h) {
                int p = mrow + mi * 16 + g + h * 8;
                float v0 = fmaf(sc0, (float)acc[mi][ni][2 * h + 0], p00);
                v0 = (v0 >= 0.f) ? v0 : al0 * v0;
                v0 += p10;
                float v1 = fmaf(sc1, (float)acc[mi][ni][2 * h + 1], p01);
                v1 = (v1 >= 0.f) ? v1 : al1 * v1;
                v1 += p11;
                outp[(size_t)oc0 * 4096 + p]       = skp[(size_t)oc0 * 4096 + p] + v0;
                outp[(size_t)(oc0 + 1) * 4096 + p] = skp[(size_t)(oc0 + 1) * 4096 + p] + v1;
            }
        }
    }
}

// ---------------- launch ----------------
extern "C" void kernel_launch(void* const* d_in, const int* in_sizes, int n_in,
                              void* d_out, int out_size) {
    const float* x      = (const float*)d_in[0];
    const float* W1     = (const float*)d_in[1];
    const float* mvk1   = (const float*)d_in[2];
    const float* mvb1   = (const float*)d_in[3];
    // d_in[4] = beta1 (forward value is sign(); beta only affects gradients)
    const float* pb0_1  = (const float*)d_in[5];
    const float* alpha1 = (const float*)d_in[6];
    const float* pb1_1  = (const float*)d_in[7];
    const float* W2     = (const float*)d_in[8];
    const float* mvk2   = (const float*)d_in[9];
    const float* mvb2   = (const float*)d_in[10];
    // d_in[11] = beta2
    const float* pb0_2  = (const float*)d_in[12];
    const float* alpha2 = (const float*)d_in[13];
    const float* pb1_2  = (const float*)d_in[14];
    float* out = (float*)d_out;

    static int configured = 0;
    cudaFuncSetAttribute(conv_imma_kernel, cudaFuncAttributeMaxDynamicSharedMemorySize, SM_DYN);
    (void)configured;

    wprep_kernel<<<256, 128>>>(W1, W2);
    poolbin_kernel<<<dim3(2, 64, 16), dim3(32, 8)>>>(x, mvk1, mvb1, mvk2, mvb2);
    zb_kernel<<<(32 * 260 * 8 + 255) / 256, 256>>>();
    conv_imma_kernel<<<dim3(32, BATCH, 2), 256, SM_DYN>>>(pb0_1, alpha1, pb1_1,
                                                          pb0_2, alpha2, pb1_2, out);
}

// round 5
// speedup vs baseline: 1.9289x; 1.9289x over previous
#include <cuda_runtime.h>
#include <cstdint>
#include <cstddef>

#define BATCH 16
#define CIN   128
#define HI    128
#define WIN   128
#define HO    64
#define WO    64

// ---------------- scratch (device globals; no allocation) ----------------
__device__ float g_pooled[BATCH * CIN * HO * WO];   // 33.5 MB (skip path)
__device__ uint4 g_xpack[2 * BATCH * HO * WO];      // 2 branches x 128-bit/pixel
__device__ uint4 g_wpack[2 * 9 * 128];              // [br][tap][oc] sign bits
__device__ int   g_wsum [2 * 9 * 128];              // [br][tap][oc] sum of signs
__device__ float g_scale[2 * 128];

// ---------------- kernel 1: weight prep ----------------
// one block per (branch, o); 128 threads = input channels
__global__ void wprep_kernel(const float* __restrict__ W1, const float* __restrict__ W2) {
    int bid = blockIdx.x;
    int br = bid >> 7, o = bid & 127;
    const float* W = br ? W2 : W1;
    int i = threadIdx.x;

    float w[9];
    float asum = 0.f;
#pragma unroll
    for (int t = 0; t < 9; ++t) {
        w[t] = W[(o * 128 + i) * 9 + t];
        asum += fabsf(w[t]);
    }

    __shared__ float red[128];
    red[i] = asum;
    __syncthreads();
    for (int s = 64; s > 0; s >>= 1) {
        if (i < s) red[i] += red[i + s];
        __syncthreads();
    }

    __shared__ __align__(16) unsigned wb[9][4];
    int lane = i & 31, wid = i >> 5;
#pragma unroll
    for (int t = 0; t < 9; ++t) {
        unsigned m = __ballot_sync(0xffffffffu, w[t] > 0.f);
        if (lane == 0) wb[t][wid] = m;
    }
    __syncthreads();

    if (i < 9) {
        uint4 v = *reinterpret_cast<uint4*>(wb[i]);
        g_wpack[(br * 9 + i) * 128 + o] = v;                 // [br][tap][oc] layout
        int ones = __popc(v.x) + __popc(v.y) + __popc(v.z) + __popc(v.w);
        g_wsum[(br * 9 + i) * 128 + o] = 2 * ones - 128;
    }
    if (i == 0) g_scale[br * 128 + o] = red[0] * (1.0f / 1152.0f);
}

// ---------------- kernel 2: fused 2x2 avg pool + binarize + bit-pack ----------------
// block (32,8); covers 32 x-pixels at one (b, y); reads x once, writes pooled + both bitplanes
__global__ void poolpack_kernel(const float* __restrict__ x,
                                const float* __restrict__ mvk1, const float* __restrict__ mvb1,
                                const float* __restrict__ mvk2, const float* __restrict__ mvb2) {
    __shared__ unsigned words[2][32][4];
    int tx = threadIdx.x, ty = threadIdx.y;
    int tid = ty * 32 + tx;
    reinterpret_cast<unsigned*>(words)[tid] = 0u;
    __syncthreads();

    int b = blockIdx.z, y = blockIdx.y, x0 = blockIdx.x * 32;
    int xo = x0 + tx;
    const float2* p = reinterpret_cast<const float2*>(x);

#pragma unroll
    for (int i = 0; i < 16; ++i) {
        int c = ty + i * 8;                                   // warp-uniform channel
        int base = ((b * CIN + c) * HI + 2 * y) * (WIN / 2) + xo;
        float2 r0 = p[base];
        float2 r1 = p[base + WIN / 2];
        float v = 0.25f * ((r0.x + r0.y) + (r1.x + r1.y));
        g_pooled[((b * CIN + c) * HO + y) * WO + xo] = v;
        unsigned bit = 1u << (c & 31);
        if (v * mvk1[c] + mvb1[c] > 0.f) atomicOr(&words[0][tx][c >> 5], bit);
        if (v * mvk2[c] + mvb2[c] > 0.f) atomicOr(&words[1][tx][c >> 5], bit);
    }
    __syncthreads();

    int br = tid >> 7;
    int rem = tid & 127;
    int px = rem >> 2, w = rem & 3;
    reinterpret_cast<unsigned*>(g_xpack)[(((br * BATCH + b) * HO + y) * WO + x0 + px) * 4 + w] =
        words[br][px][w];
}

// ---------------- kernel 3: XNOR-popcount conv + RPReLU + skip + concat ----------------
// grid (8,8,32); z = b*2+br; 256 threads; block tile = 64 px (8x8) x 128 oc
// thread = 2 px (lane, lane+32) x 16 oc (warp wid covers oc [wid*16, wid*16+16))
__global__ __launch_bounds__(256, 4) void conv_kernel(
    const float* __restrict__ pb0_1, const float* __restrict__ alpha1, const float* __restrict__ pb1_1,
    const float* __restrict__ pb0_2, const float* __restrict__ alpha2, const float* __restrict__ pb1_2,
    float* __restrict__ out) {

    __shared__ uint4 w_s[9 * 128];           // 18432 B  [tap][oc]
    __shared__ int   wsum_s[9 * 128];        //  4608 B
    __shared__ float ps[512];                //  2048 B
    __shared__ uint4 tile[100];              //  1600 B  (10x10 halo)

    int tid = threadIdx.x, wid = tid >> 5, lane = tid & 31;
    int z = blockIdx.z;
    int b = z >> 1, br = z & 1;
    int ty = blockIdx.y, tx = blockIdx.x;

    for (int k = tid; k < 1152; k += 256) {
        w_s[k] = g_wpack[br * 1152 + k];
        wsum_s[k] = g_wsum[br * 1152 + k];
    }
    if (tid < 128) {
        ps[tid]       = g_scale[br * 128 + tid];
        ps[128 + tid] = br ? pb0_2[tid]  : pb0_1[tid];
        ps[256 + tid] = br ? alpha2[tid] : alpha1[tid];
        ps[384 + tid] = br ? pb1_2[tid]  : pb1_1[tid];
    }
    for (int k = tid; k < 100; k += 256) {
        int r = k / 10, cc = k % 10;
        int gy = ty * 8 - 1 + r, gx = tx * 8 - 1 + cc;
        uint4 v = make_uint4(0, 0, 0, 0);
        if (gy >= 0 && gy < 64 && gx >= 0 && gx < 64)
            v = g_xpack[((br * BATCH + b) * HO + gy) * WO + gx];
        tile[k] = v;
    }
    __syncthreads();

    int py0 = lane >> 3, px0 = lane & 7;     // px1 is 4 rows below px0
    int gy0 = ty * 8 + py0, gx0 = tx * 8 + px0;

    // per-pixel pad masks (tap order t = (dy+1)*3 + (dx+1))
    int pm0 = 0, pm1 = 0;
    {
        int t = 0;
#pragma unroll
        for (int dy = -1; dy <= 1; ++dy)
#pragma unroll
            for (int dx = -1; dx <= 1; ++dx, ++t) {
                int yy = gy0 + dy, xx = gx0 + dx;
                if (yy < 0 || yy > 63 || xx < 0 || xx > 63) pm0 |= 1 << t;
                if (yy + 4 > 63 || xx < 0 || xx > 63)       pm1 |= 1 << t;
            }
    }

    int acc[16];                              // lo16 = px0 miss, hi16 = px1 miss
#pragma unroll
    for (int j = 0; j < 16; ++j) acc[j] = 0;

    const uint4* wbase = &w_s[wid * 16];
#pragma unroll 1
    for (int dy = -1; dy <= 1; ++dy) {
#pragma unroll 1
        for (int dx = -1; dx <= 1; ++dx) {
            uint4 in0 = tile[(py0 + 1 + dy) * 10 + (px0 + 1 + dx)];
            uint4 in1 = tile[(py0 + 5 + dy) * 10 + (px0 + 1 + dx)];
#pragma unroll
            for (int j = 0; j < 16; ++j) {
                uint4 w = wbase[j];
                int m0 = __popc(in0.x ^ w.x) + __popc(in0.y ^ w.y)
                       + __popc(in0.z ^ w.z) + __popc(in0.w ^ w.w);
                int m1 = __popc(in1.x ^ w.x) + __popc(in1.y ^ w.y)
                       + __popc(in1.z ^ w.z) + __popc(in1.w ^ w.w);
                acc[j] += m0 + (m1 << 16);
            }
            wbase += 128;
        }
    }

    // ---- epilogue ----
#pragma unroll
    for (int j = 0; j < 16; ++j) {
        int oc = wid * 16 + j;
        int a = acc[j];
        int s0 = 1152 - 2 * (a & 0xffff);
        int s1 = 1152 - 2 * (a >> 16);
        if (pm0 | pm1) {
#pragma unroll
            for (int t = 0; t < 9; ++t) {
                int ws = wsum_s[t * 128 + oc];
                if ((pm0 >> t) & 1) s0 += ws;
                if ((pm1 >> t) & 1) s1 += ws;
            }
        }
        float sc = ps[oc], b0 = ps[128 + oc], al = ps[256 + oc], b1 = ps[384 + oc];
        float v0 = fmaf(sc, (float)s0, b0);
        v0 = (v0 >= 0.f) ? v0 : al * v0;
        v0 += b1;
        float v1 = fmaf(sc, (float)s1, b0);
        v1 = (v1 >= 0.f) ? v1 : al * v1;
        v1 += b1;
        size_t o0 = ((size_t)(b * 256 + br * 128 + oc) * 64 + gy0) * 64 + gx0;
        size_t k0 = ((size_t)(b * 128 + oc) * 64 + gy0) * 64 + gx0;
        out[o0]           = g_pooled[k0]           + v0;
        out[o0 + 4 * 64]  = g_pooled[k0 + 4 * 64]  + v1;
    }
}

// ---------------- launch ----------------
extern "C" void kernel_launch(void* const* d_in, const int* in_sizes, int n_in,
                              void* d_out, int out_size) {
    const float* x      = (const float*)d_in[0];
    const float* W1     = (const float*)d_in[1];
    const float* mvk1   = (const float*)d_in[2];
    const float* mvb1   = (const float*)d_in[3];
    // d_in[4] = beta1 (forward value is sign(); beta only affects gradients)
    const float* pb0_1  = (const float*)d_in[5];
    const float* alpha1 = (const float*)d_in[6];
    const float* pb1_1  = (const float*)d_in[7];
    const float* W2     = (const float*)d_in[8];
    const float* mvk2   = (const float*)d_in[9];
    const float* mvb2   = (const float*)d_in[10];
    // d_in[11] = beta2
    const float* pb0_2  = (const float*)d_in[12];
    const float* alpha2 = (const float*)d_in[13];
    const float* pb1_2  = (const float*)d_in[14];
    float* out = (float*)d_out;

    wprep_kernel<<<256, 128>>>(W1, W2);
    poolpack_kernel<<<dim3(2, 64, 16), dim3(32, 8)>>>(x, mvk1, mvb1, mvk2, mvb2);
    conv_kernel<<<dim3(8, 8, BATCH * 2), 256>>>(pb0_1, alpha1, pb1_1,
                                                pb0_2, alpha2, pb1_2, out);
}

// round 6
// speedup vs baseline: 2.0691x; 1.0727x over previous
#include <cuda_runtime.h>
#include <cstdint>
#include <cstddef>

#define BATCH 16
#define CIN   128
#define HI    128
#define WIN   128
#define HO    64
#define WO    64

// ---------------- scratch (device globals; no allocation) ----------------
__device__ float g_pooled[BATCH * CIN * HO * WO];   // 33.5 MB (skip path)
__device__ uint4 g_xpack[2 * BATCH * HO * WO];      // 2 branches x 128-bit/pixel
__device__ uint4 g_wpack[2 * 128 * 9];              // [br][oc][tap] sign bits
__device__ int   g_wsum [2 * 128 * 9];              // [br][oc][tap] sum of signs
__device__ float g_scale[2 * 128];

// ---------------- kernel 1: weight prep ----------------
// one block per (branch, o); 128 threads = input channels
__global__ void wprep_kernel(const float* __restrict__ W1, const float* __restrict__ W2) {
    int bid = blockIdx.x;
    int br = bid >> 7, o = bid & 127;
    const float* W = br ? W2 : W1;
    int i = threadIdx.x;

    float w[9];
    float asum = 0.f;
#pragma unroll
    for (int t = 0; t < 9; ++t) {
        w[t] = W[(o * 128 + i) * 9 + t];
        asum += fabsf(w[t]);
    }

    __shared__ float red[128];
    red[i] = asum;
    __syncthreads();
    for (int s = 64; s > 0; s >>= 1) {
        if (i < s) red[i] += red[i + s];
        __syncthreads();
    }

    __shared__ __align__(16) unsigned wb[9][4];
    int lane = i & 31, wid = i >> 5;
#pragma unroll
    for (int t = 0; t < 9; ++t) {
        unsigned m = __ballot_sync(0xffffffffu, w[t] > 0.f);
        if (lane == 0) wb[t][wid] = m;
    }
    __syncthreads();

    if (i < 9) {
        uint4 v = *reinterpret_cast<uint4*>(wb[i]);
        g_wpack[(br * 128 + o) * 9 + i] = v;
        int ones = __popc(v.x) + __popc(v.y) + __popc(v.z) + __popc(v.w);
        g_wsum[(br * 128 + o) * 9 + i] = 2 * ones - 128;
    }
    if (i == 0) g_scale[br * 128 + o] = red[0] * (1.0f / 1152.0f);
}

// ---------------- kernel 2: fused 2x2 avg pool + binarize + bit-pack ----------------
// block (32,8); covers 32 x-pixels at one (b, y); ty-row owns 16 CONTIGUOUS channels
// so each thread accumulates its bit-word in a register -> 2 atomicOr total.
__global__ void poolpack_kernel(const float* __restrict__ x,
                                const float* __restrict__ mvk1, const float* __restrict__ mvb1,
                                const float* __restrict__ mvk2, const float* __restrict__ mvb2) {
    __shared__ unsigned words[2][32][4];
    int tx = threadIdx.x, ty = threadIdx.y;
    int tid = ty * 32 + tx;
    reinterpret_cast<unsigned*>(words)[tid] = 0u;
    __syncthreads();

    int b = blockIdx.z, y = blockIdx.y, x0 = blockIdx.x * 32;
    int xo = x0 + tx;
    const float2* p = reinterpret_cast<const float2*>(x);

    unsigned acc1 = 0, acc2 = 0;
#pragma unroll
    for (int i = 0; i < 16; ++i) {
        int c = ty * 16 + i;                                  // warp-uniform channel
        int base = ((b * CIN + c) * HI + 2 * y) * (WIN / 2) + xo;
        float2 r0 = p[base];
        float2 r1 = p[base + WIN / 2];
        float v = 0.25f * ((r0.x + r0.y) + (r1.x + r1.y));
        g_pooled[((b * CIN + c) * HO + y) * WO + xo] = v;
        unsigned bit = 1u << ((ty & 1) * 16 + i);             // c & 31
        if (v * mvk1[c] + mvb1[c] > 0.f) acc1 |= bit;
        if (v * mvk2[c] + mvb2[c] > 0.f) acc2 |= bit;
    }
    atomicOr(&words[0][tx][ty >> 1], acc1);
    atomicOr(&words[1][tx][ty >> 1], acc2);
    __syncthreads();

    int br = tid >> 7;
    int rem = tid & 127;
    int px = rem >> 2, w = rem & 3;
    reinterpret_cast<unsigned*>(g_xpack)[(((br * BATCH + b) * HO + y) * WO + x0 + px) * 4 + w] =
        words[br][px][w];
}

// ---------------- kernel 3: XNOR-popcount conv + RPReLU + skip + concat ----------------
// grid (8,16,32); z = b*2+br; block tile = 32 px (8x4) x 128 oc; 256 threads
// thread = 1 pixel (lane) x 16 oc (warp wid covers oc [wid*16, wid*16+16))
__global__ __launch_bounds__(256, 4) void conv_kernel(
    const float* __restrict__ pb0_1, const float* __restrict__ alpha1, const float* __restrict__ pb1_1,
    const float* __restrict__ pb0_2, const float* __restrict__ alpha2, const float* __restrict__ pb1_2,
    float* __restrict__ out) {

    __shared__ uint4 w_s[128 * 9];           // 18432 B  [oc][tap]
    __shared__ int   wsum_s[128 * 9];        //  4608 B
    __shared__ float ps[512];                //  2048 B
    __shared__ uint4 tile[60];               //   960 B  (6x10 halo)

    int tid = threadIdx.x, wid = tid >> 5, lane = tid & 31;
    int z = blockIdx.z;
    int b = z >> 1, br = z & 1;
    int ty = blockIdx.y, tx = blockIdx.x;    // y-tile 0..15 (4 rows), x-tile 0..7 (8 cols)

    for (int k = tid; k < 1152; k += 256) {
        w_s[k] = g_wpack[br * 1152 + k];
        wsum_s[k] = g_wsum[br * 1152 + k];
    }
    if (tid < 128) {
        ps[tid]       = g_scale[br * 128 + tid];
        ps[128 + tid] = br ? pb0_2[tid]  : pb0_1[tid];
        ps[256 + tid] = br ? alpha2[tid] : alpha1[tid];
        ps[384 + tid] = br ? pb1_2[tid]  : pb1_1[tid];
    }
    if (tid < 60) {
        int r = tid / 10, cc = tid % 10;
        int gy = ty * 4 - 1 + r, gx = tx * 8 - 1 + cc;
        uint4 v = make_uint4(0, 0, 0, 0);
        if (gy >= 0 && gy < 64 && gx >= 0 && gx < 64)
            v = g_xpack[((br * BATCH + b) * HO + gy) * WO + gx];
        tile[tid] = v;
    }
    __syncthreads();

    int py = lane >> 3, px = lane & 7;
    int gy = ty * 4 + py, gx = tx * 8 + px;

    uint4 in[9];
    int padmask = 0;
#pragma unroll
    for (int t = 0; t < 9; ++t) {
        int dy = t / 3 - 1, dx = t % 3 - 1;
        in[t] = tile[(py + 1 + dy) * 10 + (px + 1 + dx)];
        if (gy + dy < 0 || gy + dy > 63 || gx + dx < 0 || gx + dx > 63) padmask |= 1 << t;
    }

    const float* pooled_p = &g_pooled[(b * CIN * HO + gy) * WO + gx];
    float* out_p = &out[((b * 256 + br * 128) * HO + gy) * WO + gx];

#pragma unroll 4
    for (int j = 0; j < 16; ++j) {
        int o = (wid << 4) + j;              // 0..127, warp-uniform -> LDS broadcast
        const uint4* wp = &w_s[o * 9];
        int miss = 0;
#pragma unroll
        for (int t = 0; t < 9; ++t) {
            uint4 w = wp[t];
            miss += __popc(in[t].x ^ w.x) + __popc(in[t].y ^ w.y)
                  + __popc(in[t].z ^ w.z) + __popc(in[t].w ^ w.w);
        }
        int S = 1152 - 2 * miss;
        if (padmask) {
#pragma unroll
            for (int t = 0; t < 9; ++t)
                if (padmask & (1 << t)) S += wsum_s[o * 9 + t];
        }
        float yv = fmaf(ps[o], (float)S, ps[128 + o]);
        yv = (yv >= 0.f) ? yv : ps[256 + o] * yv;
        yv += ps[384 + o];
        out_p[o * (HO * WO)] = pooled_p[o * (HO * WO)] + yv;
    }
}

// ---------------- launch ----------------
extern "C" void kernel_launch(void* const* d_in, const int* in_sizes, int n_in,
                              void* d_out, int out_size) {
    const float* x      = (const float*)d_in[0];
    const float* W1     = (const float*)d_in[1];
    const float* mvk1   = (const float*)d_in[2];
    const float* mvb1   = (const float*)d_in[3];
    // d_in[4] = beta1 (forward value is sign(); beta only affects gradients)
    const float* pb0_1  = (const float*)d_in[5];
    const float* alpha1 = (const float*)d_in[6];
    const float* pb1_1  = (const float*)d_in[7];
    const float* W2     = (const float*)d_in[8];
    const float* mvk2   = (const float*)d_in[9];
    const float* mvb2   = (const float*)d_in[10];
    // d_in[11] = beta2
    const float* pb0_2  = (const float*)d_in[12];
    const float* alpha2 = (const float*)d_in[13];
    const float* pb1_2  = (const float*)d_in[14];
    float* out = (float*)d_out;

    wprep_kernel<<<256, 128>>>(W1, W2);
    poolpack_kernel<<<dim3(2, 64, 16), dim3(32, 8)>>>(x, mvk1, mvb1, mvk2, mvb2);
    conv_kernel<<<dim3(8, 16, BATCH * 2), 256>>>(pb0_1, alpha1, pb1_1,
                                                 pb0_2, alpha2, pb1_2, out);
}

// round 7
// speedup vs baseline: 2.3316x; 1.1268x over previous
#include <cuda_runtime.h>
#include <cstdint>
#include <cstddef>

#define BATCH 16
#define CIN   128
#define HI    128
#define WIN   128
#define HO    64
#define WO    64

// ---------------- scratch (device globals; no allocation) ----------------
__device__ float g_pooled[BATCH * CIN * HO * WO];   // 33.5 MB (skip path)
__device__ uint4 g_xpack[2 * BATCH * HO * WO];      // 2 branches x 128-bit/pixel
__device__ uint4 g_wpack[2 * 128 * 9];              // [br][oc][tap] sign bits
__device__ int   g_wsum [2 * 128 * 9];              // [br][oc][tap] sum of signs
__device__ float g_scale[2 * 128];
__device__ float g_ps[2 * 512];                     // [br][{scale,pb0,alpha,pb1} x 128]

// ---------------- CSA helpers (single LOP3 each) ----------------
__device__ __forceinline__ unsigned fa_s(unsigned a, unsigned b, unsigned c) {
    return a ^ b ^ c;
}
__device__ __forceinline__ unsigned fa_c(unsigned a, unsigned b, unsigned c) {
    return (a & b) | (c & (a | b));
}

// ---------------- kernel 1: weight prep ----------------
__global__ void wprep_kernel(const float* __restrict__ W1, const float* __restrict__ W2) {
    int bid = blockIdx.x;
    int br = bid >> 7, o = bid & 127;
    const float* W = br ? W2 : W1;
    int i = threadIdx.x;

    float w[9];
    float asum = 0.f;
#pragma unroll
    for (int t = 0; t < 9; ++t) {
        w[t] = W[(o * 128 + i) * 9 + t];
        asum += fabsf(w[t]);
    }

    __shared__ float red[128];
    red[i] = asum;
    __syncthreads();
    for (int s = 64; s > 0; s >>= 1) {
        if (i < s) red[i] += red[i + s];
        __syncthreads();
    }

    __shared__ __align__(16) unsigned wb[9][4];
    int lane = i & 31, wid = i >> 5;
#pragma unroll
    for (int t = 0; t < 9; ++t) {
        unsigned m = __ballot_sync(0xffffffffu, w[t] > 0.f);
        if (lane == 0) wb[t][wid] = m;
    }
    __syncthreads();

    if (i < 9) {
        uint4 v = *reinterpret_cast<uint4*>(wb[i]);
        g_wpack[(br * 128 + o) * 9 + i] = v;
        int ones = __popc(v.x) + __popc(v.y) + __popc(v.z) + __popc(v.w);
        g_wsum[(br * 128 + o) * 9 + i] = 2 * ones - 128;
    }
    if (i == 0) g_scale[br * 128 + o] = red[0] * (1.0f / 1152.0f);
}

// ---------------- kernel 1b: epilogue param prep ----------------
__global__ void pp_kernel(const float* __restrict__ pb0_1, const float* __restrict__ alpha1,
                          const float* __restrict__ pb1_1, const float* __restrict__ pb0_2,
                          const float* __restrict__ alpha2, const float* __restrict__ pb1_2) {
    int t = threadIdx.x;                  // 0..255
    int br = t >> 7, c = t & 127;
    g_ps[br * 512 + c]       = g_scale[br * 128 + c];
    g_ps[br * 512 + 128 + c] = br ? pb0_2[c]  : pb0_1[c];
    g_ps[br * 512 + 256 + c] = br ? alpha2[c] : alpha1[c];
    g_ps[br * 512 + 384 + c] = br ? pb1_2[c]  : pb1_1[c];
}

// ---------------- kernel 2: fused 2x2 avg pool + binarize + bit-pack ----------------
__global__ void poolpack_kernel(const float* __restrict__ x,
                                const float* __restrict__ mvk1, const float* __restrict__ mvb1,
                                const float* __restrict__ mvk2, const float* __restrict__ mvb2) {
    __shared__ unsigned words[2][32][4];
    int tx = threadIdx.x, ty = threadIdx.y;
    int tid = ty * 32 + tx;
    reinterpret_cast<unsigned*>(words)[tid] = 0u;
    __syncthreads();

    int b = blockIdx.z, y = blockIdx.y, x0 = blockIdx.x * 32;
    int xo = x0 + tx;
    const float2* p = reinterpret_cast<const float2*>(x);

    unsigned acc1 = 0, acc2 = 0;
#pragma unroll
    for (int i = 0; i < 16; ++i) {
        int c = ty * 16 + i;                                  // warp-uniform channel
        int base = ((b * CIN + c) * HI + 2 * y) * (WIN / 2) + xo;
        float2 r0 = p[base];
        float2 r1 = p[base + WIN / 2];
        float v = 0.25f * ((r0.x + r0.y) + (r1.x + r1.y));
        g_pooled[((b * CIN + c) * HO + y) * WO + xo] = v;
        unsigned bit = 1u << ((ty & 1) * 16 + i);             // c & 31
        if (v * mvk1[c] + mvb1[c] > 0.f) acc1 |= bit;
        if (v * mvk2[c] + mvb2[c] > 0.f) acc2 |= bit;
    }
    atomicOr(&words[0][tx][ty >> 1], acc1);
    atomicOr(&words[1][tx][ty >> 1], acc2);
    __syncthreads();

    int br = tid >> 7;
    int rem = tid & 127;
    int px = rem >> 2, w = rem & 3;
    reinterpret_cast<unsigned*>(g_xpack)[(((br * BATCH + b) * HO + y) * WO + x0 + px) * 4 + w] =
        words[br][px][w];
}

// ---------------- miss count via CSA compression: 36 words -> 7 POPC ----------------
__device__ __forceinline__ int csa_miss(const uint4 in[9], const uint4* __restrict__ wp) {
    unsigned v[36];
#pragma unroll
    for (int t = 0; t < 9; ++t) {
        uint4 w = wp[t];
        v[4 * t + 0] = in[t].x ^ w.x;
        v[4 * t + 1] = in[t].y ^ w.y;
        v[4 * t + 2] = in[t].z ^ w.z;
        v[4 * t + 3] = in[t].w ^ w.w;
    }
    // L1: 12 FAs over tap-triples per word lane -> 12 w1, 12 w2
    unsigned s1[12], c1[12];
#pragma unroll
    for (int g = 0; g < 3; ++g)
#pragma unroll
        for (int k = 0; k < 4; ++k) {
            unsigned a = v[(3 * g) * 4 + k], b = v[(3 * g + 1) * 4 + k], c = v[(3 * g + 2) * 4 + k];
            s1[g * 4 + k] = fa_s(a, b, c);
            c1[g * 4 + k] = fa_c(a, b, c);
        }
    // L2: w1 12 -> 4 (+4 w2)
    unsigned s2[4], c2[4];
#pragma unroll
    for (int k = 0; k < 4; ++k) {
        s2[k] = fa_s(s1[k], s1[4 + k], s1[8 + k]);
        c2[k] = fa_c(s1[k], s1[4 + k], s1[8 + k]);
    }
    // L3: w1 4 -> 2 (+1 w2)
    unsigned s3 = fa_s(s2[0], s2[1], s2[2]);
    unsigned c3 = fa_c(s2[0], s2[1], s2[2]);
    int m = __popc(s3) + __popc(s2[3]);                       // weight 1

    // W2 pool (17): c1[0..11], c2[0..3], c3  ->  1 w2 + 8 w4
    unsigned sA = fa_s(c1[0], c1[1], c1[2]),   c4a = fa_c(c1[0], c1[1], c1[2]);
    unsigned sB = fa_s(c1[3], c1[4], c1[5]),   c4b = fa_c(c1[3], c1[4], c1[5]);
    unsigned sC = fa_s(c1[6], c1[7], c1[8]),   c4c = fa_c(c1[6], c1[7], c1[8]);
    unsigned sD = fa_s(c1[9], c1[10], c1[11]), c4d = fa_c(c1[9], c1[10], c1[11]);
    unsigned sE = fa_s(c2[0], c2[1], c2[2]),   c4e = fa_c(c2[0], c2[1], c2[2]);
    unsigned sF = fa_s(sA, sB, sC),            c4f = fa_c(sA, sB, sC);
    unsigned sG = fa_s(sD, sE, c2[3]),         c4g = fa_c(sD, sE, c2[3]);
    unsigned sH = fa_s(sF, sG, c3),            c4h = fa_c(sF, sG, c3);
    m += __popc(sH) * 2;                                      // weight 2

    // W4 pool (8): c4a..c4h -> 2 w4 + 3 w8
    unsigned sI = fa_s(c4a, c4b, c4c), c8i = fa_c(c4a, c4b, c4c);
    unsigned sJ = fa_s(c4d, c4e, c4f), c8j = fa_c(c4d, c4e, c4f);
    unsigned sK = fa_s(sI, sJ, c4g),   c8k = fa_c(sI, sJ, c4g);
    m += (__popc(sK) + __popc(c4h)) * 4;                      // weight 4

    // W8 pool (3): c8i, c8j, c8k -> 1 w8 + 1 w16
    unsigned sL  = fa_s(c8i, c8j, c8k);
    unsigned c16 = fa_c(c8i, c8j, c8k);
    m += __popc(sL) * 8 + __popc(c16) * 16;                   // weights 8, 16
    return m;
}

// ---------------- kernel 3: XNOR-CSA-popcount conv + RPReLU + skip + concat ----------------
// grid (8,16,32); z = b*2+br; block tile = 32 px (8x4) x 128 oc; 256 threads
// thread = 1 pixel (lane) x 16 oc (warp wid covers oc [wid*16, wid*16+16))
__global__ __launch_bounds__(256, 3) void conv_kernel(float* __restrict__ out) {
    __shared__ uint4 w_s[128 * 9];           // 18432 B  [oc][tap]
    __shared__ int   wsum_s[128 * 9];        //  4608 B
    __shared__ float ps[512];                //  2048 B
    __shared__ uint4 tile[60];               //   960 B  (6x10 halo)

    int tid = threadIdx.x, wid = tid >> 5, lane = tid & 31;
    int z = blockIdx.z;
    int b = z >> 1, br = z & 1;
    int ty = blockIdx.y, tx = blockIdx.x;    // y-tile 0..15 (4 rows), x-tile 0..7 (8 cols)

    for (int k = tid; k < 1152; k += 256) {
        w_s[k] = g_wpack[br * 1152 + k];
        wsum_s[k] = g_wsum[br * 1152 + k];
    }
    for (int k = tid; k < 512; k += 256) ps[k] = g_ps[br * 512 + k];
    if (tid < 60) {
        int r = tid / 10, cc = tid % 10;
        int gy = ty * 4 - 1 + r, gx = tx * 8 - 1 + cc;
        uint4 v = make_uint4(0, 0, 0, 0);
        if (gy >= 0 && gy < 64 && gx >= 0 && gx < 64)
            v = g_xpack[((br * BATCH + b) * HO + gy) * WO + gx];
        tile[tid] = v;
    }
    __syncthreads();

    int py = lane >> 3, px = lane & 7;
    int gy = ty * 4 + py, gx = tx * 8 + px;

    uint4 in[9];
    int padmask = 0;
#pragma unroll
    for (int t = 0; t < 9; ++t) {
        int dy = t / 3 - 1, dx = t % 3 - 1;
        in[t] = tile[(py + 1 + dy) * 10 + (px + 1 + dx)];
        if (gy + dy < 0 || gy + dy > 63 || gx + dx < 0 || gx + dx > 63) padmask |= 1 << t;
    }

    const float* pooled_p = &g_pooled[(b * CIN * HO + gy) * WO + gx];
    float* out_p = &out[((b * 256 + br * 128) * HO + gy) * WO + gx];

#pragma unroll 2
    for (int j = 0; j < 16; ++j) {
        int o = (wid << 4) + j;              // 0..127, warp-uniform -> LDS broadcast
        int miss = csa_miss(in, &w_s[o * 9]);
        int S = 1152 - 2 * miss;
        if (padmask) {
#pragma unroll
            for (int t = 0; t < 9; ++t)
                if (padmask & (1 << t)) S += wsum_s[o * 9 + t];
        }
        float yv = fmaf(ps[o], (float)S, ps[128 + o]);
        yv = (yv >= 0.f) ? yv : ps[256 + o] * yv;
        yv += ps[384 + o];
        out_p[o * (HO * WO)] = pooled_p[o * (HO * WO)] + yv;
    }
}

// ---------------- launch ----------------
extern "C" void kernel_launch(void* const* d_in, const int* in_sizes, int n_in,
                              void* d_out, int out_size) {
    const float* x      = (const float*)d_in[0];
    const float* W1     = (const float*)d_in[1];
    const float* mvk1   = (const float*)d_in[2];
    const float* mvb1   = (const float*)d_in[3];
    // d_in[4] = beta1 (forward value is sign(); beta only affects gradients)
    const float* pb0_1  = (const float*)d_in[5];
    const float* alpha1 = (const float*)d_in[6];
    const float* pb1_1  = (const float*)d_in[7];
    const float* W2     = (const float*)d_in[8];
    const float* mvk2   = (const float*)d_in[9];
    const float* mvb2   = (const float*)d_in[10];
    // d_in[11] = beta2
    const float* pb0_2  = (const float*)d_in[12];
    const float* alpha2 = (const float*)d_in[13];
    const float* pb1_2  = (const float*)d_in[14];
    float* out = (float*)d_out;

    wprep_kernel<<<256, 128>>>(W1, W2);
    pp_kernel<<<1, 256>>>(pb0_1, alpha1, pb1_1, pb0_2, alpha2, pb1_2);
    poolpack_kernel<<<dim3(2, 64, 16), dim3(32, 8)>>>(x, mvk1, mvb1, mvk2, mvb2);
    conv_kernel<<<dim3(8, 16, BATCH * 2), 256>>>(out);
}

// round 8
// speedup vs baseline: 2.4076x; 1.0326x over previous
#include <cuda_runtime.h>
#include <cstdint>
#include <cstddef>

#define BATCH 16
#define CIN   128
#define HI    128
#define WIN   128
#define HO    64
#define WO    64

// ---------------- scratch (device globals; no allocation) ----------------
__device__ float g_pooled[BATCH * CIN * HO * WO];   // 33.5 MB (skip path)
__device__ uint4 g_xpack[2 * BATCH * HO * WO];      // 2 branches x 128-bit/pixel
__device__ uint4 g_wpack[2 * 128 * 9];              // [br][oc][tap] sign bits
__device__ int   g_wsum [2 * 128 * 9];              // [br][oc][tap] sum of signs
__device__ float g_scale[2 * 128];
__device__ float g_ps[2 * 512];                     // [br][{scale,pb0,alpha,pb1} x 128]

// ---------------- CSA helpers (single LOP3 each) ----------------
__device__ __forceinline__ unsigned fa_s(unsigned a, unsigned b, unsigned c) {
    return a ^ b ^ c;
}
__device__ __forceinline__ unsigned fa_c(unsigned a, unsigned b, unsigned c) {
    return (a & b) | (c & (a | b));
}

// ---------------- kernel 1: weight prep ----------------
__global__ void wprep_kernel(const float* __restrict__ W1, const float* __restrict__ W2) {
    int bid = blockIdx.x;
    int br = bid >> 7, o = bid & 127;
    const float* W = br ? W2 : W1;
    int i = threadIdx.x;

    float w[9];
    float asum = 0.f;
#pragma unroll
    for (int t = 0; t < 9; ++t) {
        w[t] = W[(o * 128 + i) * 9 + t];
        asum += fabsf(w[t]);
    }

    __shared__ float red[128];
    red[i] = asum;
    __syncthreads();
    for (int s = 64; s > 0; s >>= 1) {
        if (i < s) red[i] += red[i + s];
        __syncthreads();
    }

    __shared__ __align__(16) unsigned wb[9][4];
    int lane = i & 31, wid = i >> 5;
#pragma unroll
    for (int t = 0; t < 9; ++t) {
        unsigned m = __ballot_sync(0xffffffffu, w[t] > 0.f);
        if (lane == 0) wb[t][wid] = m;
    }
    __syncthreads();

    if (i < 9) {
        uint4 v = *reinterpret_cast<uint4*>(wb[i]);
        g_wpack[(br * 128 + o) * 9 + i] = v;
        int ones = __popc(v.x) + __popc(v.y) + __popc(v.z) + __popc(v.w);
        g_wsum[(br * 128 + o) * 9 + i] = 2 * ones - 128;
    }
    if (i == 0) g_scale[br * 128 + o] = red[0] * (1.0f / 1152.0f);
}

// ---------------- kernel 1b: epilogue param prep ----------------
__global__ void pp_kernel(const float* __restrict__ pb0_1, const float* __restrict__ alpha1,
                          const float* __restrict__ pb1_1, const float* __restrict__ pb0_2,
                          const float* __restrict__ alpha2, const float* __restrict__ pb1_2) {
    int t = threadIdx.x;                  // 0..255
    int br = t >> 7, c = t & 127;
    g_ps[br * 512 + c]       = g_scale[br * 128 + c];
    g_ps[br * 512 + 128 + c] = br ? pb0_2[c]  : pb0_1[c];
    g_ps[br * 512 + 256 + c] = br ? alpha2[c] : alpha1[c];
    g_ps[br * 512 + 384 + c] = br ? pb1_2[c]  : pb1_1[c];
}

// ---------------- kernel 2: fused 2x2 avg pool + binarize + bit-pack ----------------
__global__ void poolpack_kernel(const float* __restrict__ x,
                                const float* __restrict__ mvk1, const float* __restrict__ mvb1,
                                const float* __restrict__ mvk2, const float* __restrict__ mvb2) {
    __shared__ unsigned words[2][32][4];
    int tx = threadIdx.x, ty = threadIdx.y;
    int tid = ty * 32 + tx;
    reinterpret_cast<unsigned*>(words)[tid] = 0u;
    __syncthreads();

    int b = blockIdx.z, y = blockIdx.y, x0 = blockIdx.x * 32;
    int xo = x0 + tx;
    const float2* p = reinterpret_cast<const float2*>(x);

    unsigned acc1 = 0, acc2 = 0;
#pragma unroll
    for (int i = 0; i < 16; ++i) {
        int c = ty * 16 + i;                                  // warp-uniform channel
        int base = ((b * CIN + c) * HI + 2 * y) * (WIN / 2) + xo;
        float2 r0 = p[base];
        float2 r1 = p[base + WIN / 2];
        float v = 0.25f * ((r0.x + r0.y) + (r1.x + r1.y));
        g_pooled[((b * CIN + c) * HO + y) * WO + xo] = v;
        unsigned bit = 1u << ((ty & 1) * 16 + i);             // c & 31
        if (v * mvk1[c] + mvb1[c] > 0.f) acc1 |= bit;
        if (v * mvk2[c] + mvb2[c] > 0.f) acc2 |= bit;
    }
    atomicOr(&words[0][tx][ty >> 1], acc1);
    atomicOr(&words[1][tx][ty >> 1], acc2);
    __syncthreads();

    int br = tid >> 7;
    int rem = tid & 127;
    int px = rem >> 2, w = rem & 3;
    reinterpret_cast<unsigned*>(g_xpack)[(((br * BATCH + b) * HO + y) * WO + x0 + px) * 4 + w] =
        words[br][px][w];
}

// ---------------- miss count: balanced CSA (18 FA) + 18 POPC ----------------
// alu ~(36 XOR + 36 LOP3), quarter-rate popc pipe gets 18 planes -> pipes balanced
__device__ __forceinline__ int csa_miss(const uint4 in[9], const uint4* __restrict__ wp) {
    unsigned v[36];
#pragma unroll
    for (int t = 0; t < 9; ++t) {
        uint4 w = wp[t];
        v[4 * t + 0] = in[t].x ^ w.x;
        v[4 * t + 1] = in[t].y ^ w.y;
        v[4 * t + 2] = in[t].z ^ w.z;
        v[4 * t + 3] = in[t].w ^ w.w;
    }
    // L1: 12 FAs over tap-triples per word lane -> s1[12] (w1), c1[12] (w2)
    unsigned s1[12], c1[12];
#pragma unroll
    for (int g = 0; g < 3; ++g)
#pragma unroll
        for (int k = 0; k < 4; ++k) {
            unsigned a = v[12 * g + k], b = v[12 * g + 4 + k], c = v[12 * g + 8 + k];
            s1[g * 4 + k] = fa_s(a, b, c);
            c1[g * 4 + k] = fa_c(a, b, c);
        }
    // L2: 4 FAs on w1 sums -> s2[4] (w1), c2[4] (w2)
    unsigned s2[4], c2[4];
#pragma unroll
    for (int k = 0; k < 4; ++k) {
        s2[k] = fa_s(s1[k], s1[4 + k], s1[8 + k]);
        c2[k] = fa_c(s1[k], s1[4 + k], s1[8 + k]);
    }
    // 2 FAs on six w2 carries -> d0,d1 (w2), e0,e1 (w4)
    unsigned d0 = fa_s(c1[0], c1[1], c1[2]), e0 = fa_c(c1[0], c1[1], c1[2]);
    unsigned d1 = fa_s(c1[3], c1[4], c1[5]), e1 = fa_c(c1[3], c1[4], c1[5]);

    // POPC: 4 w1 + 12 w2 + 2 w4 = 18 planes
    int m1 = __popc(s2[0]) + __popc(s2[1]) + __popc(s2[2]) + __popc(s2[3]);
    int m2 = __popc(d0) + __popc(d1)
           + __popc(c1[6]) + __popc(c1[7]) + __popc(c1[8])
           + __popc(c1[9]) + __popc(c1[10]) + __popc(c1[11])
           + __popc(c2[0]) + __popc(c2[1]) + __popc(c2[2]) + __popc(c2[3]);
    int m4 = __popc(e0) + __popc(e1);
    return m1 + 2 * m2 + 4 * m4;
}

// ---------------- kernel 3: XNOR-CSA-popcount conv + RPReLU + skip + concat ----------------
// grid (8,16,32); z = b*2+br; block tile = 32 px (8x4) x 128 oc; 256 threads
// thread = 1 pixel (lane) x 16 oc (warp wid covers oc [wid*16, wid*16+16))
__global__ __launch_bounds__(256, 3) void conv_kernel(float* __restrict__ out) {
    __shared__ uint4 w_s[128 * 9];           // 18432 B  [oc][tap]
    __shared__ int   wsum_s[128 * 9];        //  4608 B
    __shared__ float ps[512];                //  2048 B
    __shared__ uint4 tile[60];               //   960 B  (6x10 halo)

    int tid = threadIdx.x, wid = tid >> 5, lane = tid & 31;
    int z = blockIdx.z;
    int b = z >> 1, br = z & 1;
    int ty = blockIdx.y, tx = blockIdx.x;    // y-tile 0..15 (4 rows), x-tile 0..7 (8 cols)

    for (int k = tid; k < 1152; k += 256) {
        w_s[k] = g_wpack[br * 1152 + k];
        wsum_s[k] = g_wsum[br * 1152 + k];
    }
    for (int k = tid; k < 512; k += 256) ps[k] = g_ps[br * 512 + k];
    if (tid < 60) {
        int r = tid / 10, cc = tid % 10;
        int gy = ty * 4 - 1 + r, gx = tx * 8 - 1 + cc;
        uint4 v = make_uint4(0, 0, 0, 0);
        if (gy >= 0 && gy < 64 && gx >= 0 && gx < 64)
            v = g_xpack[((br * BATCH + b) * HO + gy) * WO + gx];
        tile[tid] = v;
    }
    __syncthreads();

    int py = lane >> 3, px = lane & 7;
    int gy = ty * 4 + py, gx = tx * 8 + px;

    uint4 in[9];
    int padmask = 0;
#pragma unroll
    for (int t = 0; t < 9; ++t) {
        int dy = t / 3 - 1, dx = t % 3 - 1;
        in[t] = tile[(py + 1 + dy) * 10 + (px + 1 + dx)];
        if (gy + dy < 0 || gy + dy > 63 || gx + dx < 0 || gx + dx > 63) padmask |= 1 << t;
    }

    const float* pooled_p = &g_pooled[(b * CIN * HO + gy) * WO + gx];
    float* out_p = &out[((b * 256 + br * 128) * HO + gy) * WO + gx];

#pragma unroll 2
    for (int j = 0; j < 16; ++j) {
        int o = (wid << 4) + j;              // 0..127, warp-uniform -> LDS broadcast
        int miss = csa_miss(in, &w_s[o * 9]);
        int S = 1152 - 2 * miss;
        if (padmask) {
#pragma unroll
            for (int t = 0; t < 9; ++t)
                if (padmask & (1 << t)) S += wsum_s[o * 9 + t];
        }
        float yv = fmaf(ps[o], (float)S, ps[128 + o]);
        yv = (yv >= 0.f) ? yv : ps[256 + o] * yv;
        yv += ps[384 + o];
        out_p[o * (HO * WO)] = pooled_p[o * (HO * WO)] + yv;
    }
}

// ---------------- launch ----------------
extern "C" void kernel_launch(void* const* d_in, const int* in_sizes, int n_in,
                              void* d_out, int out_size) {
    const float* x      = (const float*)d_in[0];
    const float* W1     = (const float*)d_in[1];
    const float* mvk1   = (const float*)d_in[2];
    const float* mvb1   = (const float*)d_in[3];
    // d_in[4] = beta1 (forward value is sign(); beta only affects gradients)
    const float* pb0_1  = (const float*)d_in[5];
    const float* alpha1 = (const float*)d_in[6];
    const float* pb1_1  = (const float*)d_in[7];
    const float* W2     = (const float*)d_in[8];
    const float* mvk2   = (const float*)d_in[9];
    const float* mvb2   = (const float*)d_in[10];
    // d_in[11] = beta2
    const float* pb0_2  = (const float*)d_in[12];
    const float* alpha2 = (const float*)d_in[13];
    const float* pb1_2  = (const float*)d_in[14];
    float* out = (float*)d_out;

    wprep_kernel<<<256, 128>>>(W1, W2);
    pp_kernel<<<1, 256>>>(pb0_1, alpha1, pb1_1, pb0_2, alpha2, pb1_2);
    poolpack_kernel<<<dim3(2, 64, 16), dim3(32, 8)>>>(x, mvk1, mvb1, mvk2, mvb2);
    conv_kernel<<<dim3(8, 16, BATCH * 2), 256>>>(out);
}